// round 10
// baseline (speedup 1.0000x reference)
#include <cuda_runtime.h>
#include <cuda_bf16.h>
#include <cstdint>

#define N_NODES 40000
#define N_EDGES 640000
#define NFEAT   256
#define NHID    128
#define CAP     96          // per-node bucket capacity (degree ~Poisson(16), max ~48)

// ---- device-global scratch (no allocations allowed) ----
__device__ float g_support[N_NODES * NHID];     // x @ W
__device__ int   g_cnt[N_NODES];                // per-dst degree / fill cursor
__device__ int2  g_edge[(size_t)N_NODES * CAP]; // bucketed edges {src, bits(w)}

// ===========================================================================
// GEMM: support = x @ W via mma.sync m16n8k16 bf16 (tensor cores, no 'a'-gate)
// 3-term bf16 split: Ah*Bh + Ah*Bl + Al*Bh  (rel err ~1e-5)
// CTA: 256 thr (8 warps, 4Mx2N), tile M=128 N=128, K-chunk 64, TN layout.
// smem rows = 64 bf16 = 128 B, XOR-swizzled (o ^ ((row%8)<<4)) -> conflict-free.
// ===========================================================================
#define KC      64
#define SM_AH   0
#define SM_AL   16384
#define SM_BH   32768
#define SM_BL   49152
#define SM_TOT  65536
#define GEMM_CTAS ((N_NODES + 127) / 128)   // 313

__device__ __forceinline__ void mma_bf16(float* c, const uint32_t a[4],
                                         uint32_t b0, uint32_t b1) {
    asm volatile(
        "mma.sync.aligned.m16n8k16.row.col.f32.bf16.bf16.f32 "
        "{%0,%1,%2,%3}, {%4,%5,%6,%7}, {%8,%9}, {%0,%1,%2,%3};"
        : "+f"(c[0]), "+f"(c[1]), "+f"(c[2]), "+f"(c[3])
        : "r"(a[0]), "r"(a[1]), "r"(a[2]), "r"(a[3]), "r"(b0), "r"(b1));
}

__device__ __forceinline__ uint32_t pack2(__nv_bfloat16 lo, __nv_bfloat16 hi) {
    return (uint32_t)__bfloat16_as_ushort(lo) |
           ((uint32_t)__bfloat16_as_ushort(hi) << 16);
}

__global__ __launch_bounds__(256) void gemm_mma_kernel(const float* __restrict__ x,
                                                       const float* __restrict__ W) {
    extern __shared__ char sm[];
    const int tid = threadIdx.x, wid = tid >> 5, lane = tid & 31;
    const int block_row = blockIdx.x * 128;
    const int wm = wid & 3, wn = wid >> 2;     // warp tile: rows wm*32, cols wn*64
    const int g = lane >> 2, tg = lane & 3;

    float acc[2][8][4];
#pragma unroll
    for (int mt = 0; mt < 2; mt++)
#pragma unroll
        for (int nt = 0; nt < 8; nt++)
#pragma unroll
            for (int q = 0; q < 4; q++) acc[mt][nt][q] = 0.f;

    for (int c = 0; c < NFEAT / KC; c++) {     // 4 K-chunks
        const int k0 = c * KC;
        if (c > 0) __syncthreads();            // protect smem reuse

        // ---- A tile: 128 rows x 64 k  (2048 float4, 8/thread), hi/lo split ----
#pragma unroll
        for (int it = 0; it < 8; it++) {
            int idx = tid + it * 256;
            int row = idx >> 4;                // 16 float4 per row
            int c4  = idx & 15;
            int grow = block_row + row;
            if (grow > N_NODES - 1) grow = N_NODES - 1;
            float4 v = *(const float4*)(x + (size_t)grow * NFEAT + k0 + c4 * 4);
            __nv_bfloat16 h0 = __float2bfloat16_rn(v.x);
            __nv_bfloat16 h1 = __float2bfloat16_rn(v.y);
            __nv_bfloat16 h2 = __float2bfloat16_rn(v.z);
            __nv_bfloat16 h3 = __float2bfloat16_rn(v.w);
            __nv_bfloat16 l0 = __float2bfloat16_rn(v.x - __bfloat162float(h0));
            __nv_bfloat16 l1 = __float2bfloat16_rn(v.y - __bfloat162float(h1));
            __nv_bfloat16 l2 = __float2bfloat16_rn(v.z - __bfloat162float(h2));
            __nv_bfloat16 l3 = __float2bfloat16_rn(v.w - __bfloat162float(h3));
            uint32_t off = (uint32_t)(row * 128 + c4 * 8) ^ ((uint32_t)(row & 7) << 4);
            *(uint2*)(sm + SM_AH + off) = make_uint2(pack2(h0, h1), pack2(h2, h3));
            *(uint2*)(sm + SM_AL + off) = make_uint2(pack2(l0, l1), pack2(l2, l3));
        }
        // ---- B tile: Bnk[n][k] = W[k0+kk][n], transpose + split ----
#pragma unroll
        for (int it = 0; it < 8; it++) {
            int idx = tid + it * 256;
            int kk = idx >> 5;                 // 0..63
            int n4 = (idx & 31) * 4;           // 0..124
            float4 v = *(const float4*)(W + (size_t)(k0 + kk) * NHID + n4);
            float vv[4] = {v.x, v.y, v.z, v.w};
#pragma unroll
            for (int e = 0; e < 4; e++) {
                int n = n4 + e;
                __nv_bfloat16 h = __float2bfloat16_rn(vv[e]);
                __nv_bfloat16 l = __float2bfloat16_rn(vv[e] - __bfloat162float(h));
                uint32_t off = (uint32_t)(n * 128 + kk * 2) ^ ((uint32_t)(n & 7) << 4);
                *(unsigned short*)(sm + SM_BH + off) = __bfloat16_as_ushort(h);
                *(unsigned short*)(sm + SM_BL + off) = __bfloat16_as_ushort(l);
            }
        }
        __syncthreads();

        // ---- compute: 4 k-steps of 16 ----
#pragma unroll
        for (int ks = 0; ks < 4; ks++) {
            uint32_t ah[2][4], al[2][4];
#pragma unroll
            for (int mt = 0; mt < 2; mt++) {
                int r  = wm * 32 + mt * 16 + g;
                int r8 = r + 8;
                uint32_t sw  = (uint32_t)(r  & 7) << 4;
                uint32_t sw8 = (uint32_t)(r8 & 7) << 4;
                uint32_t b0 = (uint32_t)(r  * 128 + ks * 32 + tg * 4);
                uint32_t b1 = (uint32_t)(r8 * 128 + ks * 32 + tg * 4);
                ah[mt][0] = *(const uint32_t*)(sm + SM_AH + (b0 ^ sw));
                ah[mt][1] = *(const uint32_t*)(sm + SM_AH + (b1 ^ sw8));
                ah[mt][2] = *(const uint32_t*)(sm + SM_AH + ((b0 + 16) ^ sw));
                ah[mt][3] = *(const uint32_t*)(sm + SM_AH + ((b1 + 16) ^ sw8));
                al[mt][0] = *(const uint32_t*)(sm + SM_AL + (b0 ^ sw));
                al[mt][1] = *(const uint32_t*)(sm + SM_AL + (b1 ^ sw8));
                al[mt][2] = *(const uint32_t*)(sm + SM_AL + ((b0 + 16) ^ sw));
                al[mt][3] = *(const uint32_t*)(sm + SM_AL + ((b1 + 16) ^ sw8));
            }
#pragma unroll
            for (int nt = 0; nt < 8; nt++) {
                int n = wn * 64 + nt * 8 + g;
                uint32_t sw = (uint32_t)(n & 7) << 4;
                uint32_t bo = (uint32_t)(n * 128 + ks * 32 + tg * 4);
                uint32_t bh0 = *(const uint32_t*)(sm + SM_BH + (bo ^ sw));
                uint32_t bh1 = *(const uint32_t*)(sm + SM_BH + ((bo + 16) ^ sw));
                uint32_t bl0 = *(const uint32_t*)(sm + SM_BL + (bo ^ sw));
                uint32_t bl1 = *(const uint32_t*)(sm + SM_BL + ((bo + 16) ^ sw));
#pragma unroll
                for (int mt = 0; mt < 2; mt++) {
                    mma_bf16(acc[mt][nt], ah[mt], bh0, bh1);   // Ah*Bh
                    mma_bf16(acc[mt][nt], ah[mt], bl0, bl1);   // Ah*Bl
                    mma_bf16(acc[mt][nt], al[mt], bh0, bh1);   // Al*Bh
                }
            }
        }
    }

    // ---- epilogue: fragments -> g_support (float2 stores, sector-aligned) ----
#pragma unroll
    for (int mt = 0; mt < 2; mt++) {
        int r0 = block_row + wm * 32 + mt * 16 + g;
        int r8 = r0 + 8;
#pragma unroll
        for (int nt = 0; nt < 8; nt++) {
            int col = wn * 64 + nt * 8 + tg * 2;
            if (r0 < N_NODES)
                *(float2*)(g_support + (size_t)r0 * NHID + col) =
                    make_float2(acc[mt][nt][0], acc[mt][nt][1]);
            if (r8 < N_NODES)
                *(float2*)(g_support + (size_t)r8 * NHID + col) =
                    make_float2(acc[mt][nt][2], acc[mt][nt][3]);
        }
    }
}

// ===========================================================================
// Edge bucketing: memset(g_cnt) -> fill (no scans).
// ===========================================================================
__global__ __launch_bounds__(256) void fill_kernel(const int* __restrict__ ei,
                                                   const float* __restrict__ ew) {
    int i = blockIdx.x * 256 + threadIdx.x;
    if (i >= N_EDGES) return;
    int src = ei[i];
    int dst = ei[N_EDGES + i];
    int slot = atomicAdd(&g_cnt[dst], 1);
    if (slot < CAP)
        g_edge[(size_t)dst * CAP + slot] = make_int2(src, __float_as_int(ew[i]));
}

// ===========================================================================
// Aggregate: one warp per dst node; 4-edge unroll; fused bias+relu.
// ===========================================================================
__global__ __launch_bounds__(256) void aggregate_kernel(const float* __restrict__ b,
                                                        float* __restrict__ out) {
    const int warp = (blockIdx.x * 256 + threadIdx.x) >> 5;
    const int lane = threadIdx.x & 31;
    if (warp >= N_NODES) return;

    const size_t base = (size_t)warp * CAP;
    int n = g_cnt[warp];
    if (n > CAP) n = CAP;

    float4 a0 = make_float4(0.f, 0.f, 0.f, 0.f);
    float4 a1 = make_float4(0.f, 0.f, 0.f, 0.f);
    float4 a2 = make_float4(0.f, 0.f, 0.f, 0.f);
    float4 a3 = make_float4(0.f, 0.f, 0.f, 0.f);

    int j = 0;
    for (; j + 4 <= n; j += 4) {
        int2 e0 = __ldg(&g_edge[base + j]);
        int2 e1 = __ldg(&g_edge[base + j + 1]);
        int2 e2 = __ldg(&g_edge[base + j + 2]);
        int2 e3 = __ldg(&g_edge[base + j + 3]);
        float4 v0 = *(const float4*)(g_support + (size_t)e0.x * NHID + lane * 4);
        float4 v1 = *(const float4*)(g_support + (size_t)e1.x * NHID + lane * 4);
        float4 v2 = *(const float4*)(g_support + (size_t)e2.x * NHID + lane * 4);
        float4 v3 = *(const float4*)(g_support + (size_t)e3.x * NHID + lane * 4);
        float w0 = __int_as_float(e0.y), w1 = __int_as_float(e1.y);
        float w2 = __int_as_float(e2.y), w3 = __int_as_float(e3.y);
        a0.x = fmaf(v0.x, w0, a0.x); a0.y = fmaf(v0.y, w0, a0.y);
        a0.z = fmaf(v0.z, w0, a0.z); a0.w = fmaf(v0.w, w0, a0.w);
        a1.x = fmaf(v1.x, w1, a1.x); a1.y = fmaf(v1.y, w1, a1.y);
        a1.z = fmaf(v1.z, w1, a1.z); a1.w = fmaf(v1.w, w1, a1.w);
        a2.x = fmaf(v2.x, w2, a2.x); a2.y = fmaf(v2.y, w2, a2.y);
        a2.z = fmaf(v2.z, w2, a2.z); a2.w = fmaf(v2.w, w2, a2.w);
        a3.x = fmaf(v3.x, w3, a3.x); a3.y = fmaf(v3.y, w3, a3.y);
        a3.z = fmaf(v3.z, w3, a3.z); a3.w = fmaf(v3.w, w3, a3.w);
    }
    for (; j < n; j++) {
        int2 e0 = __ldg(&g_edge[base + j]);
        float w0 = __int_as_float(e0.y);
        float4 v0 = *(const float4*)(g_support + (size_t)e0.x * NHID + lane * 4);
        a0.x = fmaf(v0.x, w0, a0.x); a0.y = fmaf(v0.y, w0, a0.y);
        a0.z = fmaf(v0.z, w0, a0.z); a0.w = fmaf(v0.w, w0, a0.w);
    }

    float4 bb = *(const float4*)(b + lane * 4);
    float4 r;
    r.x = fmaxf(a0.x + a1.x + a2.x + a3.x + bb.x, 0.f);
    r.y = fmaxf(a0.y + a1.y + a2.y + a3.y + bb.y, 0.f);
    r.z = fmaxf(a0.z + a1.z + a2.z + a3.z + bb.z, 0.f);
    r.w = fmaxf(a0.w + a1.w + a2.w + a3.w + bb.w, 0.f);
    *(float4*)(out + (size_t)warp * NHID + lane * 4) = r;
}

// ===========================================================================
extern "C" void kernel_launch(void* const* d_in, const int* in_sizes, int n_in,
                              void* d_out, int out_size) {
    const float* x  = (const float*)d_in[0];
    const int*   ei = (const int*)d_in[1];     // int32 on device
    const float* ew = (const float*)d_in[2];
    const float* W  = (const float*)d_in[3];
    const float* b  = (const float*)d_in[4];
    float*       out = (float*)d_out;

    const int EDGE_BLKS = (N_EDGES + 255) / 256;

    static cudaStream_t s2 = nullptr;
    static cudaEvent_t evFork = nullptr, evJoin = nullptr;
    if (!s2) {
        cudaStreamCreateWithFlags(&s2, cudaStreamNonBlocking);
        cudaEventCreateWithFlags(&evFork, cudaEventDisableTiming);
        cudaEventCreateWithFlags(&evJoin, cudaEventDisableTiming);
        cudaFuncSetAttribute(gemm_mma_kernel,
                             cudaFuncAttributeMaxDynamicSharedMemorySize, SM_TOT);
    }
    void* cnt_ptr;
    cudaGetSymbolAddress(&cnt_ptr, g_cnt);

    // fork: edge bucketing on s2, tensor-core GEMM on the main stream
    cudaEventRecord(evFork, 0);
    cudaStreamWaitEvent(s2, evFork, 0);

    gemm_mma_kernel<<<GEMM_CTAS, 256, SM_TOT>>>(x, W);

    cudaMemsetAsync(cnt_ptr, 0, N_NODES * sizeof(int), s2);
    fill_kernel<<<EDGE_BLKS, 256, 0, s2>>>(ei, ew);

    // join: aggregate needs support (main) + buckets (s2)
    cudaEventRecord(evJoin, s2);
    cudaStreamWaitEvent(0, evJoin, 0);

    aggregate_kernel<<<(N_NODES * 32 + 255) / 256, 256>>>(b, out);
}

// round 11
// speedup vs baseline: 1.3422x; 1.3422x over previous
#include <cuda_runtime.h>
#include <cuda_bf16.h>
#include <cstdint>

#define N_NODES 40000
#define N_EDGES 640000
#define NFEAT   256
#define NHID    128
#define CAP     96          // per-node bucket capacity (degree ~Poisson(16), max ~48)

// ---- device-global scratch (no allocations allowed) ----
__device__ float g_support[N_NODES * NHID];     // x @ W
__device__ int   g_cnt[N_NODES];                // per-dst degree / fill cursor
__device__ int2  g_edge[(size_t)N_NODES * CAP]; // bucketed edges {src, bits(w)}
__device__ __nv_bfloat16 g_xh[(size_t)N_NODES * NFEAT];   // hi(x)
__device__ __nv_bfloat16 g_xl[(size_t)N_NODES * NFEAT];   // lo(x)
__device__ __nv_bfloat16 g_wht[(size_t)NHID * NFEAT];     // hi(W^T)
__device__ __nv_bfloat16 g_wlt[(size_t)NHID * NFEAT];     // lo(W^T)

// ===========================================================================
// helpers
// ===========================================================================
__device__ __forceinline__ uint32_t smem_u32(const void* p) {
    uint32_t a;
    asm("{ .reg .u64 t; cvta.to.shared.u64 t, %1; cvt.u32.u64 %0, t; }" : "=r"(a) : "l"(p));
    return a;
}
__device__ __forceinline__ void mma_bf16(float* c, const uint32_t a[4],
                                         uint32_t b0, uint32_t b1) {
    asm volatile(
        "mma.sync.aligned.m16n8k16.row.col.f32.bf16.bf16.f32 "
        "{%0,%1,%2,%3}, {%4,%5,%6,%7}, {%8,%9}, {%0,%1,%2,%3};"
        : "+f"(c[0]), "+f"(c[1]), "+f"(c[2]), "+f"(c[3])
        : "r"(a[0]), "r"(a[1]), "r"(a[2]), "r"(a[3]), "r"(b0), "r"(b1));
}
__device__ __forceinline__ void ldm_x4(uint32_t* r, uint32_t addr) {
    asm volatile("ldmatrix.sync.aligned.m8n8.x4.shared.b16 {%0,%1,%2,%3}, [%4];"
        : "=r"(r[0]), "=r"(r[1]), "=r"(r[2]), "=r"(r[3]) : "r"(addr));
}
__device__ __forceinline__ void cp16(uint32_t dst, const void* src) {
    asm volatile("cp.async.cg.shared.global [%0], [%1], 16;"
        :: "r"(dst), "l"(__cvta_generic_to_global(src)));
}

// ===========================================================================
// Pre-split: x -> (xh, xl) bf16 ; W -> transposed (wht, wlt) bf16
// ===========================================================================
__global__ __launch_bounds__(256) void split_x_kernel(const float* __restrict__ x) {
    int i = blockIdx.x * 256 + threadIdx.x;        // float4 index (2.56M total)
    float4 v = ((const float4*)x)[i];
    __nv_bfloat16 h[4], l[4];
    float vv[4] = {v.x, v.y, v.z, v.w};
#pragma unroll
    for (int e = 0; e < 4; e++) {
        h[e] = __float2bfloat16_rn(vv[e]);
        l[e] = __float2bfloat16_rn(vv[e] - __bfloat162float(h[e]));
    }
    ((uint2*)g_xh)[i] = make_uint2(
        (uint32_t)__bfloat16_as_ushort(h[0]) | ((uint32_t)__bfloat16_as_ushort(h[1]) << 16),
        (uint32_t)__bfloat16_as_ushort(h[2]) | ((uint32_t)__bfloat16_as_ushort(h[3]) << 16));
    ((uint2*)g_xl)[i] = make_uint2(
        (uint32_t)__bfloat16_as_ushort(l[0]) | ((uint32_t)__bfloat16_as_ushort(l[1]) << 16),
        (uint32_t)__bfloat16_as_ushort(l[2]) | ((uint32_t)__bfloat16_as_ushort(l[3]) << 16));
}

__global__ __launch_bounds__(256) void split_w_kernel(const float* __restrict__ W) {
    int i = blockIdx.x * 256 + threadIdx.x;        // 32768 elements
    int k = i >> 7, n = i & 127;
    float v = W[i];
    __nv_bfloat16 h = __float2bfloat16_rn(v);
    __nv_bfloat16 l = __float2bfloat16_rn(v - __bfloat162float(h));
    g_wht[(size_t)n * NFEAT + k] = h;
    g_wlt[(size_t)n * NFEAT + k] = l;
}

// ===========================================================================
// GEMM: mma.sync bf16, 3-term split, cp.async double-buffer, ldmatrix frags.
// CTA 256 thr (8 warps, warp tile 32x64), M=128 N=128, KC=32 (8 chunks).
// smem rows: 32 bf16 = 64B data @ 80B stride (conflict-free ldmatrix).
// ===========================================================================
#define KC      32
#define NCH     (NFEAT / KC)      // 8
#define STRIDE  80
#define TILE    (128 * STRIDE)    // 10240
#define STAGE   (4 * TILE)        // 40960: AH AL BH BL
#define SM_TOT  (2 * STAGE)       // 81920
#define GEMM_CTAS ((N_NODES + 127) / 128)   // 313

__global__ __launch_bounds__(256, 2) void gemm_mma_kernel() {
    extern __shared__ char sm[];
    const uint32_t sb = smem_u32(sm);
    const int tid = threadIdx.x, wid = tid >> 5, lane = tid & 31;
    const int block_row = blockIdx.x * 128;
    const int wm = wid & 3, wn = wid >> 2;      // warp tile: rows wm*32, cols wn*64
    const int g = lane >> 2, tg = lane & 3;
    const int lr = (lane & 7) + ((lane >> 3) & 1) * 8;   // ldmatrix row-in-16
    const int kb = lane >> 4;                             // ldmatrix k-block

    float acc[2][8][4];
#pragma unroll
    for (int mt = 0; mt < 2; mt++)
#pragma unroll
        for (int nt = 0; nt < 8; nt++)
#pragma unroll
            for (int q = 0; q < 4; q++) acc[mt][nt][q] = 0.f;

    // ---- prefetch one K-chunk into buffer `buf` (2048 x 16B cp.async) ----
    auto prefetch = [&](int c, int buf) {
        const uint32_t base = sb + buf * STAGE;
        const int k0 = c * KC;
#pragma unroll
        for (int t = 0; t < 8; t++) {
            int idx = tid + t * 256;             // 0..2047
            int tile = idx >> 9;                 // 0:AH 1:AL 2:BH 3:BL
            int i = idx & 511;
            int row = i >> 2;
            int cc = i & 3;
            uint32_t dst = base + tile * TILE + row * STRIDE + cc * 16;
            const __nv_bfloat16* src;
            if (tile < 2) {
                int grow = block_row + row;
                if (grow >= N_NODES) grow = N_NODES - 1;
                src = (tile == 0 ? g_xh : g_xl) + (size_t)grow * NFEAT + k0 + cc * 8;
            } else {
                src = (tile == 2 ? g_wht : g_wlt) + (size_t)row * NFEAT + k0 + cc * 8;
            }
            cp16(dst, src);
        }
        asm volatile("cp.async.commit_group;" ::: "memory");
    };

    prefetch(0, 0);
    for (int c = 0; c < NCH; c++) {
        if (c + 1 < NCH) {
            prefetch(c + 1, (c + 1) & 1);
            asm volatile("cp.async.wait_group 1;" ::: "memory");
        } else {
            asm volatile("cp.async.wait_group 0;" ::: "memory");
        }
        __syncthreads();

        const uint32_t base = sb + (c & 1) * STAGE;
#pragma unroll
        for (int ks = 0; ks < 2; ks++) {         // two k16 steps per chunk
            uint32_t ah[2][4], al[2][4];
#pragma unroll
            for (int mt = 0; mt < 2; mt++) {
                uint32_t off = (uint32_t)((wm * 32 + mt * 16 + lr) * STRIDE + ks * 32 + kb * 16);
                ldm_x4(ah[mt], base + off);
                ldm_x4(al[mt], base + TILE + off);
            }
#pragma unroll
            for (int nt2 = 0; nt2 < 4; nt2++) {
                uint32_t off = (uint32_t)((wn * 64 + nt2 * 16 + lr) * STRIDE + ks * 32 + kb * 16);
                uint32_t bh[4], bl[4];
                ldm_x4(bh, base + 2 * TILE + off);
                ldm_x4(bl, base + 3 * TILE + off);
#pragma unroll
                for (int half = 0; half < 2; half++) {
                    int nt = nt2 * 2 + half;
#pragma unroll
                    for (int mt = 0; mt < 2; mt++) {
                        mma_bf16(acc[mt][nt], ah[mt], bh[half], bh[2 + half]);  // Ah*Bh
                        mma_bf16(acc[mt][nt], ah[mt], bl[half], bl[2 + half]);  // Ah*Bl
                        mma_bf16(acc[mt][nt], al[mt], bh[half], bh[2 + half]);  // Al*Bh
                    }
                }
            }
        }
        __syncthreads();                          // buffer reuse fence
    }

    // ---- epilogue: fragments -> g_support ----
#pragma unroll
    for (int mt = 0; mt < 2; mt++) {
        int r0 = block_row + wm * 32 + mt * 16 + g;
        int r8 = r0 + 8;
#pragma unroll
        for (int nt = 0; nt < 8; nt++) {
            int col = wn * 64 + nt * 8 + tg * 2;
            if (r0 < N_NODES)
                *(float2*)(g_support + (size_t)r0 * NHID + col) =
                    make_float2(acc[mt][nt][0], acc[mt][nt][1]);
            if (r8 < N_NODES)
                *(float2*)(g_support + (size_t)r8 * NHID + col) =
                    make_float2(acc[mt][nt][2], acc[mt][nt][3]);
        }
    }
}

// ===========================================================================
// Edge bucketing: memset(g_cnt) -> fill (no scans).
// ===========================================================================
__global__ __launch_bounds__(256) void fill_kernel(const int* __restrict__ ei,
                                                   const float* __restrict__ ew) {
    int i = blockIdx.x * 256 + threadIdx.x;
    if (i >= N_EDGES) return;
    int src = ei[i];
    int dst = ei[N_EDGES + i];
    int slot = atomicAdd(&g_cnt[dst], 1);
    if (slot < CAP)
        g_edge[(size_t)dst * CAP + slot] = make_int2(src, __float_as_int(ew[i]));
}

// ===========================================================================
// Aggregate: one warp per dst node; 4-edge unroll; fused bias+relu.
// ===========================================================================
__global__ __launch_bounds__(256) void aggregate_kernel(const float* __restrict__ b,
                                                        float* __restrict__ out) {
    const int warp = (blockIdx.x * 256 + threadIdx.x) >> 5;
    const int lane = threadIdx.x & 31;
    if (warp >= N_NODES) return;

    const size_t base = (size_t)warp * CAP;
    int n = g_cnt[warp];
    if (n > CAP) n = CAP;

    float4 a0 = make_float4(0.f, 0.f, 0.f, 0.f);
    float4 a1 = make_float4(0.f, 0.f, 0.f, 0.f);
    float4 a2 = make_float4(0.f, 0.f, 0.f, 0.f);
    float4 a3 = make_float4(0.f, 0.f, 0.f, 0.f);

    int j = 0;
    for (; j + 4 <= n; j += 4) {
        int2 e0 = __ldg(&g_edge[base + j]);
        int2 e1 = __ldg(&g_edge[base + j + 1]);
        int2 e2 = __ldg(&g_edge[base + j + 2]);
        int2 e3 = __ldg(&g_edge[base + j + 3]);
        float4 v0 = *(const float4*)(g_support + (size_t)e0.x * NHID + lane * 4);
        float4 v1 = *(const float4*)(g_support + (size_t)e1.x * NHID + lane * 4);
        float4 v2 = *(const float4*)(g_support + (size_t)e2.x * NHID + lane * 4);
        float4 v3 = *(const float4*)(g_support + (size_t)e3.x * NHID + lane * 4);
        float w0 = __int_as_float(e0.y), w1 = __int_as_float(e1.y);
        float w2 = __int_as_float(e2.y), w3 = __int_as_float(e3.y);
        a0.x = fmaf(v0.x, w0, a0.x); a0.y = fmaf(v0.y, w0, a0.y);
        a0.z = fmaf(v0.z, w0, a0.z); a0.w = fmaf(v0.w, w0, a0.w);
        a1.x = fmaf(v1.x, w1, a1.x); a1.y = fmaf(v1.y, w1, a1.y);
        a1.z = fmaf(v1.z, w1, a1.z); a1.w = fmaf(v1.w, w1, a1.w);
        a2.x = fmaf(v2.x, w2, a2.x); a2.y = fmaf(v2.y, w2, a2.y);
        a2.z = fmaf(v2.z, w2, a2.z); a2.w = fmaf(v2.w, w2, a2.w);
        a3.x = fmaf(v3.x, w3, a3.x); a3.y = fmaf(v3.y, w3, a3.y);
        a3.z = fmaf(v3.z, w3, a3.z); a3.w = fmaf(v3.w, w3, a3.w);
    }
    for (; j < n; j++) {
        int2 e0 = __ldg(&g_edge[base + j]);
        float w0 = __int_as_float(e0.y);
        float4 v0 = *(const float4*)(g_support + (size_t)e0.x * NHID + lane * 4);
        a0.x = fmaf(v0.x, w0, a0.x); a0.y = fmaf(v0.y, w0, a0.y);
        a0.z = fmaf(v0.z, w0, a0.z); a0.w = fmaf(v0.w, w0, a0.w);
    }

    float4 bb = *(const float4*)(b + lane * 4);
    float4 r;
    r.x = fmaxf(a0.x + a1.x + a2.x + a3.x + bb.x, 0.f);
    r.y = fmaxf(a0.y + a1.y + a2.y + a3.y + bb.y, 0.f);
    r.z = fmaxf(a0.z + a1.z + a2.z + a3.z + bb.z, 0.f);
    r.w = fmaxf(a0.w + a1.w + a2.w + a3.w + bb.w, 0.f);
    *(float4*)(out + (size_t)warp * NHID + lane * 4) = r;
}

// ===========================================================================
extern "C" void kernel_launch(void* const* d_in, const int* in_sizes, int n_in,
                              void* d_out, int out_size) {
    const float* x  = (const float*)d_in[0];
    const int*   ei = (const int*)d_in[1];     // int32 on device
    const float* ew = (const float*)d_in[2];
    const float* W  = (const float*)d_in[3];
    const float* b  = (const float*)d_in[4];
    float*       out = (float*)d_out;

    const int EDGE_BLKS = (N_EDGES + 255) / 256;

    static cudaStream_t s2 = nullptr;
    static cudaEvent_t evFork = nullptr, evJoin = nullptr;
    if (!s2) {
        cudaStreamCreateWithFlags(&s2, cudaStreamNonBlocking);
        cudaEventCreateWithFlags(&evFork, cudaEventDisableTiming);
        cudaEventCreateWithFlags(&evJoin, cudaEventDisableTiming);
        cudaFuncSetAttribute(gemm_mma_kernel,
                             cudaFuncAttributeMaxDynamicSharedMemorySize, SM_TOT);
    }
    void* cnt_ptr;
    cudaGetSymbolAddress(&cnt_ptr, g_cnt);

    // fork: edge bucketing on s2; split + GEMM on the main stream
    cudaEventRecord(evFork, 0);
    cudaStreamWaitEvent(s2, evFork, 0);

    split_x_kernel<<<(N_NODES * NFEAT / 4) / 256, 256>>>(x);
    split_w_kernel<<<(NFEAT * NHID) / 256, 256>>>(W);
    gemm_mma_kernel<<<GEMM_CTAS, 256, SM_TOT>>>();

    cudaMemsetAsync(cnt_ptr, 0, N_NODES * sizeof(int), s2);
    fill_kernel<<<EDGE_BLKS, 256, 0, s2>>>(ei, ew);

    // join: aggregate needs support (main) + buckets (s2)
    cudaEventRecord(evJoin, s2);
    cudaStreamWaitEvent(0, evJoin, 0);

    aggregate_kernel<<<(N_NODES * 32 + 255) / 256, 256>>>(b, out);
}

// round 13
// speedup vs baseline: 1.4503x; 1.0805x over previous
#include <cuda_runtime.h>
#include <cuda_bf16.h>
#include <cstdint>

#define N_NODES 40000
#define N_EDGES 640000
#define NFEAT   256
#define NHID    128
#define CAP     96          // per-node bucket capacity (degree ~Poisson(16), max ~48)

// ---- device-global scratch (no allocations allowed) ----
__device__ float g_support[N_NODES * NHID];     // x @ W
__device__ int   g_cnt[N_NODES];                // per-dst degree / fill cursor
__device__ int2  g_edge[(size_t)N_NODES * CAP]; // bucketed edges {src, bits(w)}
__device__ __nv_bfloat16 g_wht[(size_t)NHID * NFEAT];     // hi(W^T)  [n][k]
__device__ __nv_bfloat16 g_wlt[(size_t)NHID * NFEAT];     // lo(W^T)  [n][k]

// ===========================================================================
// helpers
// ===========================================================================
__device__ __forceinline__ uint32_t smem_u32(const void* p) {
    uint32_t a;
    asm("{ .reg .u64 t; cvta.to.shared.u64 t, %1; cvt.u32.u64 %0, t; }" : "=r"(a) : "l"(p));
    return a;
}
__device__ __forceinline__ void mma_bf16(float* c, const uint32_t a[4],
                                         uint32_t b0, uint32_t b1) {
    asm volatile(
        "mma.sync.aligned.m16n8k16.row.col.f32.bf16.bf16.f32 "
        "{%0,%1,%2,%3}, {%4,%5,%6,%7}, {%8,%9}, {%0,%1,%2,%3};"
        : "+f"(c[0]), "+f"(c[1]), "+f"(c[2]), "+f"(c[3])
        : "r"(a[0]), "r"(a[1]), "r"(a[2]), "r"(a[3]), "r"(b0), "r"(b1));
}
__device__ __forceinline__ void ldm_x4(uint32_t* r, uint32_t addr) {
    asm volatile("ldmatrix.sync.aligned.m8n8.x4.shared.b16 {%0,%1,%2,%3}, [%4];"
        : "=r"(r[0]), "=r"(r[1]), "=r"(r[2]), "=r"(r[3]) : "r"(addr));
}
__device__ __forceinline__ void cp16(uint32_t dst, const void* src) {
    asm volatile("cp.async.cg.shared.global [%0], [%1], 16;"
        :: "r"(dst), "l"(__cvta_generic_to_global(src)));
}
__device__ __forceinline__ uint32_t packh(float a, float b) {
    return (uint32_t)__bfloat16_as_ushort(__float2bfloat16_rn(a)) |
           ((uint32_t)__bfloat16_as_ushort(__float2bfloat16_rn(b)) << 16);
}

// ===========================================================================
// Pre-split W -> transposed (wht, wlt) bf16  (tiny: 32768 elements)
// ===========================================================================
__global__ __launch_bounds__(256) void split_w_kernel(const float* __restrict__ W) {
    int i = blockIdx.x * 256 + threadIdx.x;
    int k = i >> 7, n = i & 127;
    float v = W[i];
    __nv_bfloat16 h = __float2bfloat16_rn(v);
    __nv_bfloat16 l = __float2bfloat16_rn(v - __bfloat162float(h));
    g_wht[(size_t)n * NFEAT + k] = h;
    g_wlt[(size_t)n * NFEAT + k] = l;
}

// ===========================================================================
// GEMM: persistent CTAs (grid=148), W hi/lo resident in smem (stride 528,
// ldmatrix-conflict-free), A fp32 register-staged -> in-register bf16 split ->
// STS double-buffered (stride 80). 3-term mma.sync bf16.
// ===========================================================================
#define NTILES  ((N_NODES + 127) / 128)   // 313
#define STRW    528
#define STRA    80
#define SM_WH   0
#define SM_WL   (128 * STRW)              // 67584
#define SM_A    (2 * 128 * STRW)          // 135168
#define ABUF    (2 * 128 * STRA)          // 20480 (AH + AL)
#define SM_TOT  (SM_A + 2 * ABUF)         // 176128

__global__ __launch_bounds__(256) void gemm_mma_kernel(const float* __restrict__ x) {
    extern __shared__ char sm[];
    const uint32_t sb = smem_u32(sm);
    const int tid = threadIdx.x, wid = tid >> 5, lane = tid & 31;
    const int wm = wid & 3, wn = wid >> 2;      // warp tile: rows wm*32, cols wn*64
    const int g = lane >> 2, tg = lane & 3;
    const int lr = (lane & 7) + ((lane >> 3) & 1) * 8;   // ldmatrix row-in-16
    const int kb = lane >> 4;                             // ldmatrix k-half

    // ---- load W hi/lo into smem once (cp.async, 16B x 4096 per tile) ----
#pragma unroll
    for (int t = 0; t < 16; t++) {
        int idx = tid + t * 256;           // 0..4095
        int n = idx >> 5, cc = idx & 31;
        cp16(sb + SM_WH + n * STRW + cc * 16, g_wht + (size_t)n * NFEAT + cc * 8);
        cp16(sb + SM_WL + n * STRW + cc * 16, g_wlt + (size_t)n * NFEAT + cc * 8);
    }
    asm volatile("cp.async.commit_group;" ::: "memory");

    // per-thread A staging mapping: 4 float4 of the 128x32 fp32 chunk
    const int ar[4] = {(tid + 0)   >> 3, (tid + 256) >> 3,
                       (tid + 512) >> 3, (tid + 768) >> 3};
    const int ac = tid & 7;               // float4 col within row (same all t)

    bool wwait = true;
    for (int tile = blockIdx.x; tile < NTILES; tile += gridDim.x) {
        const int block_row = tile * 128;

        float acc[2][8][4];
#pragma unroll
        for (int mt = 0; mt < 2; mt++)
#pragma unroll
            for (int nt = 0; nt < 8; nt++)
#pragma unroll
                for (int q = 0; q < 4; q++) acc[mt][nt][q] = 0.f;

        float4 pre[4];
        auto ldA = [&](int c) {
#pragma unroll
            for (int t = 0; t < 4; t++) {
                int grow = block_row + ar[t];
                if (grow >= N_NODES) grow = N_NODES - 1;
                pre[t] = *(const float4*)(x + (size_t)grow * NFEAT + c * 32 + ac * 4);
            }
        };
        auto stA = [&](int buf) {
            const uint32_t ab = sb + SM_A + buf * ABUF;
#pragma unroll
            for (int t = 0; t < 4; t++) {
                float4 v = pre[t];
                uint32_t off = (uint32_t)(ar[t] * STRA + ac * 8);
                float hx = __bfloat162float(__float2bfloat16_rn(v.x));
                float hy = __bfloat162float(__float2bfloat16_rn(v.y));
                float hz = __bfloat162float(__float2bfloat16_rn(v.z));
                float hw = __bfloat162float(__float2bfloat16_rn(v.w));
                *(uint2*)(sm + (ab - sb) + off) =
                    make_uint2(packh(v.x, v.y), packh(v.z, v.w));
                *(uint2*)(sm + (ab - sb) + 128 * STRA + off) =
                    make_uint2(packh(v.x - hx, v.y - hy), packh(v.z - hz, v.w - hw));
            }
        };
        auto compute = [&](int c, int buf) {
            const uint32_t ab = sb + SM_A + buf * ABUF;
#pragma unroll
            for (int ks = 0; ks < 2; ks++) {
                uint32_t ah[2][4], al[2][4];
#pragma unroll
                for (int mt = 0; mt < 2; mt++) {
                    uint32_t off = (uint32_t)((wm * 32 + mt * 16 + lr) * STRA + ks * 32 + kb * 16);
                    ldm_x4(ah[mt], ab + off);
                    ldm_x4(al[mt], ab + 128 * STRA + off);
                }
                const uint32_t kB = (uint32_t)(c * 64 + ks * 32 + kb * 16);
#pragma unroll
                for (int nt2 = 0; nt2 < 4; nt2++) {
                    uint32_t off = (uint32_t)((wn * 64 + nt2 * 16 + lr) * STRW) + kB;
                    uint32_t bh[4], bl[4];
                    ldm_x4(bh, sb + SM_WH + off);
                    ldm_x4(bl, sb + SM_WL + off);
#pragma unroll
                    for (int half = 0; half < 2; half++) {
                        int nt = nt2 * 2 + half;
#pragma unroll
                        for (int mt = 0; mt < 2; mt++) {
                            mma_bf16(acc[mt][nt], ah[mt], bh[half], bh[2 + half]);
                            mma_bf16(acc[mt][nt], ah[mt], bl[half], bl[2 + half]);
                            mma_bf16(acc[mt][nt], al[mt], bh[half], bh[2 + half]);
                        }
                    }
                }
            }
        };

        // prologue: chunk 0 into buf 0
        ldA(0);
        stA(0);
        if (wwait) {
            asm volatile("cp.async.wait_group 0;" ::: "memory");
            wwait = false;
        }
        __syncthreads();

        for (int c = 0; c < 8; c++) {
            if (c < 7) ldA(c + 1);            // LDG latency hidden by mma below
            compute(c, c & 1);
            __syncthreads();
            if (c < 7) {
                stA((c + 1) & 1);
                __syncthreads();
            }
        }

        // epilogue: fragments -> g_support
#pragma unroll
        for (int mt = 0; mt < 2; mt++) {
            int r0 = block_row + wm * 32 + mt * 16 + g;
            int r8 = r0 + 8;
#pragma unroll
            for (int nt = 0; nt < 8; nt++) {
                int col = wn * 64 + nt * 8 + tg * 2;
                if (r0 < N_NODES)
                    *(float2*)(g_support + (size_t)r0 * NHID + col) =
                        make_float2(acc[mt][nt][0], acc[mt][nt][1]);
                if (r8 < N_NODES)
                    *(float2*)(g_support + (size_t)r8 * NHID + col) =
                        make_float2(acc[mt][nt][2], acc[mt][nt][3]);
            }
        }
    }
}

// ===========================================================================
// Edge bucketing: memset(g_cnt) -> fill (no scans).
// ===========================================================================
__global__ __launch_bounds__(256) void fill_kernel(const int* __restrict__ ei,
                                                   const float* __restrict__ ew) {
    int i = blockIdx.x * 256 + threadIdx.x;
    if (i >= N_EDGES) return;
    int src = ei[i];
    int dst = ei[N_EDGES + i];
    int slot = atomicAdd(&g_cnt[dst], 1);
    if (slot < CAP)
        g_edge[(size_t)dst * CAP + slot] = make_int2(src, __float_as_int(ew[i]));
}

// ===========================================================================
// Aggregate: one warp per dst node; 4-edge unroll; fused bias+relu.
// ===========================================================================
__global__ __launch_bounds__(256) void aggregate_kernel(const float* __restrict__ b,
                                                        float* __restrict__ out) {
    const int warp = (blockIdx.x * 256 + threadIdx.x) >> 5;
    const int lane = threadIdx.x & 31;
    if (warp >= N_NODES) return;

    const size_t base = (size_t)warp * CAP;
    int n = g_cnt[warp];
    if (n > CAP) n = CAP;

    float4 a0 = make_float4(0.f, 0.f, 0.f, 0.f);
    float4 a1 = make_float4(0.f, 0.f, 0.f, 0.f);
    float4 a2 = make_float4(0.f, 0.f, 0.f, 0.f);
    float4 a3 = make_float4(0.f, 0.f, 0.f, 0.f);

    int j = 0;
    for (; j + 4 <= n; j += 4) {
        int2 e0 = __ldg(&g_edge[base + j]);
        int2 e1 = __ldg(&g_edge[base + j + 1]);
        int2 e2 = __ldg(&g_edge[base + j + 2]);
        int2 e3 = __ldg(&g_edge[base + j + 3]);
        float4 v0 = *(const float4*)(g_support + (size_t)e0.x * NHID + lane * 4);
        float4 v1 = *(const float4*)(g_support + (size_t)e1.x * NHID + lane * 4);
        float4 v2 = *(const float4*)(g_support + (size_t)e2.x * NHID + lane * 4);
        float4 v3 = *(const float4*)(g_support + (size_t)e3.x * NHID + lane * 4);
        float w0 = __int_as_float(e0.y), w1 = __int_as_float(e1.y);
        float w2 = __int_as_float(e2.y), w3 = __int_as_float(e3.y);
        a0.x = fmaf(v0.x, w0, a0.x); a0.y = fmaf(v0.y, w0, a0.y);
        a0.z = fmaf(v0.z, w0, a0.z); a0.w = fmaf(v0.w, w0, a0.w);
        a1.x = fmaf(v1.x, w1, a1.x); a1.y = fmaf(v1.y, w1, a1.y);
        a1.z = fmaf(v1.z, w1, a1.z); a1.w = fmaf(v1.w, w1, a1.w);
        a2.x = fmaf(v2.x, w2, a2.x); a2.y = fmaf(v2.y, w2, a2.y);
        a2.z = fmaf(v2.z, w2, a2.z); a2.w = fmaf(v2.w, w2, a2.w);
        a3.x = fmaf(v3.x, w3, a3.x); a3.y = fmaf(v3.y, w3, a3.y);
        a3.z = fmaf(v3.z, w3, a3.z); a3.w = fmaf(v3.w, w3, a3.w);
    }
    for (; j < n; j++) {
        int2 e0 = __ldg(&g_edge[base + j]);
        float w0 = __int_as_float(e0.y);
        float4 v0 = *(const float4*)(g_support + (size_t)e0.x * NHID + lane * 4);
        a0.x = fmaf(v0.x, w0, a0.x); a0.y = fmaf(v0.y, w0, a0.y);
        a0.z = fmaf(v0.z, w0, a0.z); a0.w = fmaf(v0.w, w0, a0.w);
    }

    float4 bb = *(const float4*)(b + lane * 4);
    float4 r;
    r.x = fmaxf(a0.x + a1.x + a2.x + a3.x + bb.x, 0.f);
    r.y = fmaxf(a0.y + a1.y + a2.y + a3.y + bb.y, 0.f);
    r.z = fmaxf(a0.z + a1.z + a2.z + a3.z + bb.z, 0.f);
    r.w = fmaxf(a0.w + a1.w + a2.w + a3.w + bb.w, 0.f);
    *(float4*)(out + (size_t)warp * NHID + lane * 4) = r;
}

// ===========================================================================
extern "C" void kernel_launch(void* const* d_in, const int* in_sizes, int n_in,
                              void* d_out, int out_size) {
    const float* x  = (const float*)d_in[0];
    const int*   ei = (const int*)d_in[1];     // int32 on device
    const float* ew = (const float*)d_in[2];
    const float* W  = (const float*)d_in[3];
    const float* b  = (const float*)d_in[4];
    float*       out = (float*)d_out;

    const int EDGE_BLKS = (N_EDGES + 255) / 256;

    static cudaStream_t s2 = nullptr;
    static cudaEvent_t evFork = nullptr, evJoin = nullptr;
    if (!s2) {
        cudaStreamCreateWithFlags(&s2, cudaStreamNonBlocking);
        cudaEventCreateWithFlags(&evFork, cudaEventDisableTiming);
        cudaEventCreateWithFlags(&evJoin, cudaEventDisableTiming);
        cudaFuncSetAttribute(gemm_mma_kernel,
                             cudaFuncAttributeMaxDynamicSharedMemorySize, SM_TOT);
    }
    void* cnt_ptr;
    cudaGetSymbolAddress(&cnt_ptr, g_cnt);

    // fork: edge bucketing on s2; split_w + GEMM on the main stream
    cudaEventRecord(evFork, 0);
    cudaStreamWaitEvent(s2, evFork, 0);

    split_w_kernel<<<(NFEAT * NHID) / 256, 256>>>(W);
    gemm_mma_kernel<<<148, 256, SM_TOT>>>(x);

    cudaMemsetAsync(cnt_ptr, 0, N_NODES * sizeof(int), s2);
    fill_kernel<<<EDGE_BLKS, 256, 0, s2>>>(ei, ew);

    // join: aggregate needs support (main) + buckets (s2)
    cudaEventRecord(evJoin, s2);
    cudaStreamWaitEvent(0, evJoin, 0);

    aggregate_kernel<<<(N_NODES * 32 + 255) / 256, 256>>>(b, out);
}

// round 14
// speedup vs baseline: 1.5063x; 1.0386x over previous
#include <cuda_runtime.h>
#include <cuda_bf16.h>
#include <cuda_fp16.h>
#include <cstdint>

#define N_NODES 40000
#define N_EDGES 640000
#define NFEAT   256
#define NHID    128
#define CAP     96          // per-node bucket capacity (degree ~Poisson(16), max ~48)

// ---- device-global scratch (no allocations allowed) ----
__device__ __half g_support[(size_t)N_NODES * NHID];  // x @ W  (fp16 messages)
__device__ int   g_cnt[N_NODES];                // per-dst degree / fill cursor
__device__ int2  g_edge[(size_t)N_NODES * CAP]; // bucketed edges {src, bits(w)}
__device__ __nv_bfloat16 g_wht[(size_t)NHID * NFEAT];     // hi(W^T)  [n][k]
__device__ __nv_bfloat16 g_wlt[(size_t)NHID * NFEAT];     // lo(W^T)  [n][k]

// ===========================================================================
// helpers
// ===========================================================================
__device__ __forceinline__ uint32_t smem_u32(const void* p) {
    uint32_t a;
    asm("{ .reg .u64 t; cvta.to.shared.u64 t, %1; cvt.u32.u64 %0, t; }" : "=r"(a) : "l"(p));
    return a;
}
__device__ __forceinline__ void mma_bf16(float* c, const uint32_t a[4],
                                         uint32_t b0, uint32_t b1) {
    asm volatile(
        "mma.sync.aligned.m16n8k16.row.col.f32.bf16.bf16.f32 "
        "{%0,%1,%2,%3}, {%4,%5,%6,%7}, {%8,%9}, {%0,%1,%2,%3};"
        : "+f"(c[0]), "+f"(c[1]), "+f"(c[2]), "+f"(c[3])
        : "r"(a[0]), "r"(a[1]), "r"(a[2]), "r"(a[3]), "r"(b0), "r"(b1));
}
__device__ __forceinline__ void ldm_x4(uint32_t* r, uint32_t addr) {
    asm volatile("ldmatrix.sync.aligned.m8n8.x4.shared.b16 {%0,%1,%2,%3}, [%4];"
        : "=r"(r[0]), "=r"(r[1]), "=r"(r[2]), "=r"(r[3]) : "r"(addr));
}
__device__ __forceinline__ void cp16(uint32_t dst, const void* src) {
    asm volatile("cp.async.cg.shared.global [%0], [%1], 16;"
        :: "r"(dst), "l"(__cvta_generic_to_global(src)));
}
__device__ __forceinline__ uint32_t packh(float a, float b) {
    return (uint32_t)__bfloat16_as_ushort(__float2bfloat16_rn(a)) |
           ((uint32_t)__bfloat16_as_ushort(__float2bfloat16_rn(b)) << 16);
}

// ===========================================================================
// Pre-split W -> transposed (wht, wlt) bf16  (tiny: 32768 elements)
// ===========================================================================
__global__ __launch_bounds__(256) void split_w_kernel(const float* __restrict__ W) {
    int i = blockIdx.x * 256 + threadIdx.x;
    int k = i >> 7, n = i & 127;
    float v = W[i];
    __nv_bfloat16 h = __float2bfloat16_rn(v);
    __nv_bfloat16 l = __float2bfloat16_rn(v - __bfloat162float(h));
    g_wht[(size_t)n * NFEAT + k] = h;
    g_wlt[(size_t)n * NFEAT + k] = l;
}

// ===========================================================================
// GEMM: persistent CTAs (grid=148), W hi/lo resident in smem (stride 528,
// ldmatrix-conflict-free), A fp32 register-staged -> in-register bf16 split ->
// STS double-buffered (stride 80). 3-term mma.sync bf16. fp16 epilogue.
// ===========================================================================
#define NTILES  ((N_NODES + 127) / 128)   // 313
#define STRW    528
#define STRA    80
#define SM_WH   0
#define SM_WL   (128 * STRW)              // 67584
#define SM_A    (2 * 128 * STRW)          // 135168
#define ABUF    (2 * 128 * STRA)          // 20480 (AH + AL)
#define SM_TOT  (SM_A + 2 * ABUF)         // 176128

__global__ __launch_bounds__(256) void gemm_mma_kernel(const float* __restrict__ x) {
    extern __shared__ char sm[];
    const uint32_t sb = smem_u32(sm);
    const int tid = threadIdx.x, wid = tid >> 5, lane = tid & 31;
    const int wm = wid & 3, wn = wid >> 2;      // warp tile: rows wm*32, cols wn*64
    const int g = lane >> 2, tg = lane & 3;
    const int lr = (lane & 7) + ((lane >> 3) & 1) * 8;   // ldmatrix row-in-16
    const int kb = lane >> 4;                             // ldmatrix k-half

    // ---- load W hi/lo into smem once (cp.async, 16B x 4096 per tile) ----
#pragma unroll
    for (int t = 0; t < 16; t++) {
        int idx = tid + t * 256;           // 0..4095
        int n = idx >> 5, cc = idx & 31;
        cp16(sb + SM_WH + n * STRW + cc * 16, g_wht + (size_t)n * NFEAT + cc * 8);
        cp16(sb + SM_WL + n * STRW + cc * 16, g_wlt + (size_t)n * NFEAT + cc * 8);
    }
    asm volatile("cp.async.commit_group;" ::: "memory");

    // per-thread A staging mapping: 4 float4 of the 128x32 fp32 chunk
    const int ar[4] = {(tid + 0)   >> 3, (tid + 256) >> 3,
                       (tid + 512) >> 3, (tid + 768) >> 3};
    const int ac = tid & 7;               // float4 col within row (same all t)

    bool wwait = true;
    for (int tile = blockIdx.x; tile < NTILES; tile += gridDim.x) {
        const int block_row = tile * 128;

        float acc[2][8][4];
#pragma unroll
        for (int mt = 0; mt < 2; mt++)
#pragma unroll
            for (int nt = 0; nt < 8; nt++)
#pragma unroll
                for (int q = 0; q < 4; q++) acc[mt][nt][q] = 0.f;

        float4 pre[4];
        auto ldA = [&](int c) {
#pragma unroll
            for (int t = 0; t < 4; t++) {
                int grow = block_row + ar[t];
                if (grow >= N_NODES) grow = N_NODES - 1;
                pre[t] = *(const float4*)(x + (size_t)grow * NFEAT + c * 32 + ac * 4);
            }
        };
        auto stA = [&](int buf) {
            const uint32_t ab = sb + SM_A + buf * ABUF;
#pragma unroll
            for (int t = 0; t < 4; t++) {
                float4 v = pre[t];
                uint32_t off = (uint32_t)(ar[t] * STRA + ac * 8);
                float hx = __bfloat162float(__float2bfloat16_rn(v.x));
                float hy = __bfloat162float(__float2bfloat16_rn(v.y));
                float hz = __bfloat162float(__float2bfloat16_rn(v.z));
                float hw = __bfloat162float(__float2bfloat16_rn(v.w));
                *(uint2*)(sm + (ab - sb) + off) =
                    make_uint2(packh(v.x, v.y), packh(v.z, v.w));
                *(uint2*)(sm + (ab - sb) + 128 * STRA + off) =
                    make_uint2(packh(v.x - hx, v.y - hy), packh(v.z - hz, v.w - hw));
            }
        };
        auto compute = [&](int c, int buf) {
            const uint32_t ab = sb + SM_A + buf * ABUF;
#pragma unroll
            for (int ks = 0; ks < 2; ks++) {
                uint32_t ah[2][4], al[2][4];
#pragma unroll
                for (int mt = 0; mt < 2; mt++) {
                    uint32_t off = (uint32_t)((wm * 32 + mt * 16 + lr) * STRA + ks * 32 + kb * 16);
                    ldm_x4(ah[mt], ab + off);
                    ldm_x4(al[mt], ab + 128 * STRA + off);
                }
                const uint32_t kB = (uint32_t)(c * 64 + ks * 32 + kb * 16);
#pragma unroll
                for (int nt2 = 0; nt2 < 4; nt2++) {
                    uint32_t off = (uint32_t)((wn * 64 + nt2 * 16 + lr) * STRW) + kB;
                    uint32_t bh[4], bl[4];
                    ldm_x4(bh, sb + SM_WH + off);
                    ldm_x4(bl, sb + SM_WL + off);
#pragma unroll
                    for (int half = 0; half < 2; half++) {
                        int nt = nt2 * 2 + half;
#pragma unroll
                        for (int mt = 0; mt < 2; mt++) {
                            mma_bf16(acc[mt][nt], ah[mt], bh[half], bh[2 + half]);
                            mma_bf16(acc[mt][nt], ah[mt], bl[half], bl[2 + half]);
                            mma_bf16(acc[mt][nt], al[mt], bh[half], bh[2 + half]);
                        }
                    }
                }
            }
        };

        // prologue: chunk 0 into buf 0
        ldA(0);
        stA(0);
        if (wwait) {
            asm volatile("cp.async.wait_group 0;" ::: "memory");
            wwait = false;
        }
        __syncthreads();

        for (int c = 0; c < 8; c++) {
            if (c < 7) ldA(c + 1);            // LDG latency hidden by mma below
            compute(c, c & 1);
            __syncthreads();
            if (c < 7) {
                stA((c + 1) & 1);
                __syncthreads();
            }
        }

        // epilogue: fragments -> g_support (fp16, packed half2 stores)
#pragma unroll
        for (int mt = 0; mt < 2; mt++) {
            int r0 = block_row + wm * 32 + mt * 16 + g;
            int r8 = r0 + 8;
#pragma unroll
            for (int nt = 0; nt < 8; nt++) {
                int col = wn * 64 + nt * 8 + tg * 2;
                if (r0 < N_NODES) {
                    __half2 h = __floats2half2_rn(acc[mt][nt][0], acc[mt][nt][1]);
                    *(__half2*)(g_support + (size_t)r0 * NHID + col) = h;
                }
                if (r8 < N_NODES) {
                    __half2 h = __floats2half2_rn(acc[mt][nt][2], acc[mt][nt][3]);
                    *(__half2*)(g_support + (size_t)r8 * NHID + col) = h;
                }
            }
        }
    }
}

// ===========================================================================
// Edge bucketing: memset(g_cnt) -> fill (no scans).
// ===========================================================================
__global__ __launch_bounds__(256) void fill_kernel(const int* __restrict__ ei,
                                                   const float* __restrict__ ew) {
    int i = blockIdx.x * 256 + threadIdx.x;
    if (i >= N_EDGES) return;
    int src = ei[i];
    int dst = ei[N_EDGES + i];
    int slot = atomicAdd(&g_cnt[dst], 1);
    if (slot < CAP)
        g_edge[(size_t)dst * CAP + slot] = make_int2(src, __float_as_int(ew[i]));
}

// ===========================================================================
// Aggregate: one warp per dst node; fp16 gather (uint2 = 4 halves per lane),
// fp32 accumulation; 4-edge unroll; fused bias+relu.
// ===========================================================================
__global__ __launch_bounds__(256) void aggregate_kernel(const float* __restrict__ b,
                                                        float* __restrict__ out) {
    const int warp = (blockIdx.x * 256 + threadIdx.x) >> 5;
    const int lane = threadIdx.x & 31;
    if (warp >= N_NODES) return;

    const size_t base = (size_t)warp * CAP;
    int n = g_cnt[warp];
    if (n > CAP) n = CAP;

    float4 a0 = make_float4(0.f, 0.f, 0.f, 0.f);
    float4 a1 = make_float4(0.f, 0.f, 0.f, 0.f);
    float4 a2 = make_float4(0.f, 0.f, 0.f, 0.f);
    float4 a3 = make_float4(0.f, 0.f, 0.f, 0.f);

    auto fma_edge = [&](int2 e, float4& a) {
        float w = __int_as_float(e.y);
        uint2 u = *(const uint2*)(g_support + (size_t)e.x * NHID + lane * 4);
        float2 f0 = __half22float2(*(__half2*)&u.x);
        float2 f1 = __half22float2(*(__half2*)&u.y);
        a.x = fmaf(f0.x, w, a.x);
        a.y = fmaf(f0.y, w, a.y);
        a.z = fmaf(f1.x, w, a.z);
        a.w = fmaf(f1.y, w, a.w);
    };

    int j = 0;
    for (; j + 4 <= n; j += 4) {
        int2 e0 = __ldg(&g_edge[base + j]);
        int2 e1 = __ldg(&g_edge[base + j + 1]);
        int2 e2 = __ldg(&g_edge[base + j + 2]);
        int2 e3 = __ldg(&g_edge[base + j + 3]);
        fma_edge(e0, a0);
        fma_edge(e1, a1);
        fma_edge(e2, a2);
        fma_edge(e3, a3);
    }
    for (; j < n; j++) {
        int2 e0 = __ldg(&g_edge[base + j]);
        fma_edge(e0, a0);
    }

    float4 bb = *(const float4*)(b + lane * 4);
    float4 r;
    r.x = fmaxf(a0.x + a1.x + a2.x + a3.x + bb.x, 0.f);
    r.y = fmaxf(a0.y + a1.y + a2.y + a3.y + bb.y, 0.f);
    r.z = fmaxf(a0.z + a1.z + a2.z + a3.z + bb.z, 0.f);
    r.w = fmaxf(a0.w + a1.w + a2.w + a3.w + bb.w, 0.f);
    *(float4*)(out + (size_t)warp * NHID + lane * 4) = r;
}

// ===========================================================================
extern "C" void kernel_launch(void* const* d_in, const int* in_sizes, int n_in,
                              void* d_out, int out_size) {
    const float* x  = (const float*)d_in[0];
    const int*   ei = (const int*)d_in[1];     // int32 on device
    const float* ew = (const float*)d_in[2];
    const float* W  = (const float*)d_in[3];
    const float* b  = (const float*)d_in[4];
    float*       out = (float*)d_out;

    const int EDGE_BLKS = (N_EDGES + 255) / 256;

    static cudaStream_t s2 = nullptr;
    static cudaEvent_t evFork = nullptr, evJoin = nullptr;
    if (!s2) {
        cudaStreamCreateWithFlags(&s2, cudaStreamNonBlocking);
        cudaEventCreateWithFlags(&evFork, cudaEventDisableTiming);
        cudaEventCreateWithFlags(&evJoin, cudaEventDisableTiming);
        cudaFuncSetAttribute(gemm_mma_kernel,
                             cudaFuncAttributeMaxDynamicSharedMemorySize, SM_TOT);
    }
    void* cnt_ptr;
    cudaGetSymbolAddress(&cnt_ptr, g_cnt);

    // fork: edge bucketing on s2; split_w + GEMM on the main stream
    cudaEventRecord(evFork, 0);
    cudaStreamWaitEvent(s2, evFork, 0);

    split_w_kernel<<<(NFEAT * NHID) / 256, 256>>>(W);
    gemm_mma_kernel<<<148, 256, SM_TOT>>>(x);

    cudaMemsetAsync(cnt_ptr, 0, N_NODES * sizeof(int), s2);
    fill_kernel<<<EDGE_BLKS, 256, 0, s2>>>(ei, ew);

    // join: aggregate needs support (main) + buckets (s2)
    cudaEventRecord(evJoin, s2);
    cudaStreamWaitEvent(0, evJoin, 0);

    aggregate_kernel<<<(N_NODES * 32 + 255) / 256, 256>>>(b, out);
}

// round 16
// speedup vs baseline: 1.5500x; 1.0290x over previous
#include <cuda_runtime.h>
#include <cuda_bf16.h>
#include <cuda_fp16.h>
#include <cstdint>

#define N_NODES 40000
#define N_EDGES 640000
#define NFEAT   256
#define NHID    128
#define CAP     96          // per-node bucket capacity (degree ~Poisson(16), max ~48)

// ---- device-global scratch (no allocations allowed) ----
__device__ __half g_support[(size_t)N_NODES * NHID];  // x @ W  (fp16 messages)
__device__ int   g_cnt[N_NODES];                // per-dst degree / fill cursor
__device__ int2  g_edge[(size_t)N_NODES * CAP]; // bucketed edges {src, bits(w)}
__device__ __nv_bfloat16 g_wht[(size_t)NHID * NFEAT];     // hi(W^T)  [n][k]
__device__ __nv_bfloat16 g_wlt[(size_t)NHID * NFEAT];     // lo(W^T)  [n][k]

// ===========================================================================
// helpers
// ===========================================================================
__device__ __forceinline__ uint32_t smem_u32(const void* p) {
    uint32_t a;
    asm("{ .reg .u64 t; cvta.to.shared.u64 t, %1; cvt.u32.u64 %0, t; }" : "=r"(a) : "l"(p));
    return a;
}
__device__ __forceinline__ void mma_bf16(float* c, const uint32_t a[4],
                                         uint32_t b0, uint32_t b1) {
    asm volatile(
        "mma.sync.aligned.m16n8k16.row.col.f32.bf16.bf16.f32 "
        "{%0,%1,%2,%3}, {%4,%5,%6,%7}, {%8,%9}, {%0,%1,%2,%3};"
        : "+f"(c[0]), "+f"(c[1]), "+f"(c[2]), "+f"(c[3])
        : "r"(a[0]), "r"(a[1]), "r"(a[2]), "r"(a[3]), "r"(b0), "r"(b1));
}
__device__ __forceinline__ void ldm_x4(uint32_t* r, uint32_t addr) {
    asm volatile("ldmatrix.sync.aligned.m8n8.x4.shared.b16 {%0,%1,%2,%3}, [%4];"
        : "=r"(r[0]), "=r"(r[1]), "=r"(r[2]), "=r"(r[3]) : "r"(addr));
}
__device__ __forceinline__ void cp16(uint32_t dst, const void* src) {
    asm volatile("cp.async.cg.shared.global [%0], [%1], 16;"
        :: "r"(dst), "l"(__cvta_generic_to_global(src)));
}
__device__ __forceinline__ uint32_t packh(float a, float b) {
    return (uint32_t)__bfloat16_as_ushort(__float2bfloat16_rn(a)) |
           ((uint32_t)__bfloat16_as_ushort(__float2bfloat16_rn(b)) << 16);
}

// ===========================================================================
// Pre-split W -> transposed (wht, wlt) bf16  (tiny: 32768 elements)
// ===========================================================================
__global__ __launch_bounds__(256) void split_w_kernel(const float* __restrict__ W) {
    int i = blockIdx.x * 256 + threadIdx.x;
    int k = i >> 7, n = i & 127;
    float v = W[i];
    __nv_bfloat16 h = __float2bfloat16_rn(v);
    __nv_bfloat16 l = __float2bfloat16_rn(v - __bfloat162float(h));
    g_wht[(size_t)n * NFEAT + k] = h;
    g_wlt[(size_t)n * NFEAT + k] = l;
}

// ===========================================================================
// GEMM: persistent CTAs (grid=148), W hi/lo resident in smem (stride 528,
// ldmatrix-conflict-free), A fp32 register-staged -> in-register bf16 split ->
// STS double-buffered (stride 80). 3-term mma.sync bf16. fp16 epilogue.
// ===========================================================================
#define NTILES  ((N_NODES + 127) / 128)   // 313
#define STRW    528
#define STRA    80
#define SM_WH   0
#define SM_WL   (128 * STRW)              // 67584
#define SM_A    (2 * 128 * STRW)          // 135168
#define ABUF    (2 * 128 * STRA)          // 20480 (AH + AL)
#define SM_TOT  (SM_A + 2 * ABUF)         // 176128

__global__ __launch_bounds__(256) void gemm_mma_kernel(const float* __restrict__ x) {
    extern __shared__ char sm[];
    const uint32_t sb = smem_u32(sm);
    const int tid = threadIdx.x, wid = tid >> 5, lane = tid & 31;
    const int wm = wid & 3, wn = wid >> 2;      // warp tile: rows wm*32, cols wn*64
    const int g = lane >> 2, tg = lane & 3;
    const int lr = (lane & 7) + ((lane >> 3) & 1) * 8;   // ldmatrix row-in-16
    const int kb = lane >> 4;                             // ldmatrix k-half

    // ---- load W hi/lo into smem once (cp.async, 16B x 4096 per tile) ----
#pragma unroll
    for (int t = 0; t < 16; t++) {
        int idx = tid + t * 256;           // 0..4095
        int n = idx >> 5, cc = idx & 31;
        cp16(sb + SM_WH + n * STRW + cc * 16, g_wht + (size_t)n * NFEAT + cc * 8);
        cp16(sb + SM_WL + n * STRW + cc * 16, g_wlt + (size_t)n * NFEAT + cc * 8);
    }
    asm volatile("cp.async.commit_group;" ::: "memory");

    // per-thread A staging mapping: 4 float4 of the 128x32 fp32 chunk
    const int ar[4] = {(tid + 0)   >> 3, (tid + 256) >> 3,
                       (tid + 512) >> 3, (tid + 768) >> 3};
    const int ac = tid & 7;               // float4 col within row (same all t)

    bool wwait = true;
    for (int tile = blockIdx.x; tile < NTILES; tile += gridDim.x) {
        const int block_row = tile * 128;

        float acc[2][8][4];
#pragma unroll
        for (int mt = 0; mt < 2; mt++)
#pragma unroll
            for (int nt = 0; nt < 8; nt++)
#pragma unroll
                for (int q = 0; q < 4; q++) acc[mt][nt][q] = 0.f;

        float4 pre[4];
        auto ldA = [&](int c) {
#pragma unroll
            for (int t = 0; t < 4; t++) {
                int grow = block_row + ar[t];
                if (grow >= N_NODES) grow = N_NODES - 1;
                pre[t] = *(const float4*)(x + (size_t)grow * NFEAT + c * 32 + ac * 4);
            }
        };
        auto stA = [&](int buf) {
            const uint32_t ab = sb + SM_A + buf * ABUF;
#pragma unroll
            for (int t = 0; t < 4; t++) {
                float4 v = pre[t];
                uint32_t off = (uint32_t)(ar[t] * STRA + ac * 8);
                float hx = __bfloat162float(__float2bfloat16_rn(v.x));
                float hy = __bfloat162float(__float2bfloat16_rn(v.y));
                float hz = __bfloat162float(__float2bfloat16_rn(v.z));
                float hw = __bfloat162float(__float2bfloat16_rn(v.w));
                *(uint2*)(sm + (ab - sb) + off) =
                    make_uint2(packh(v.x, v.y), packh(v.z, v.w));
                *(uint2*)(sm + (ab - sb) + 128 * STRA + off) =
                    make_uint2(packh(v.x - hx, v.y - hy), packh(v.z - hz, v.w - hw));
            }
        };
        auto compute = [&](int c, int buf) {
            const uint32_t ab = sb + SM_A + buf * ABUF;
#pragma unroll
            for (int ks = 0; ks < 2; ks++) {
                uint32_t ah[2][4], al[2][4];
#pragma unroll
                for (int mt = 0; mt < 2; mt++) {
                    uint32_t off = (uint32_t)((wm * 32 + mt * 16 + lr) * STRA + ks * 32 + kb * 16);
                    ldm_x4(ah[mt], ab + off);
                    ldm_x4(al[mt], ab + 128 * STRA + off);
                }
                const uint32_t kB = (uint32_t)(c * 64 + ks * 32 + kb * 16);
#pragma unroll
                for (int nt2 = 0; nt2 < 4; nt2++) {
                    uint32_t off = (uint32_t)((wn * 64 + nt2 * 16 + lr) * STRW) + kB;
                    uint32_t bh[4], bl[4];
                    ldm_x4(bh, sb + SM_WH + off);
                    ldm_x4(bl, sb + SM_WL + off);
#pragma unroll
                    for (int half = 0; half < 2; half++) {
                        int nt = nt2 * 2 + half;
#pragma unroll
                        for (int mt = 0; mt < 2; mt++) {
                            mma_bf16(acc[mt][nt], ah[mt], bh[half], bh[2 + half]);
                            mma_bf16(acc[mt][nt], ah[mt], bl[half], bl[2 + half]);
                            mma_bf16(acc[mt][nt], al[mt], bh[half], bh[2 + half]);
                        }
                    }
                }
            }
        };

        // prologue: chunk 0 into buf 0
        ldA(0);
        stA(0);
        if (wwait) {
            asm volatile("cp.async.wait_group 0;" ::: "memory");
            wwait = false;
        }
        __syncthreads();

        for (int c = 0; c < 8; c++) {
            if (c < 7) ldA(c + 1);            // LDG latency hidden by mma below
            compute(c, c & 1);
            __syncthreads();
            if (c < 7) {
                stA((c + 1) & 1);
                __syncthreads();
            }
        }

        // epilogue: fragments -> g_support (fp16, packed half2 stores)
#pragma unroll
        for (int mt = 0; mt < 2; mt++) {
            int r0 = block_row + wm * 32 + mt * 16 + g;
            int r8 = r0 + 8;
#pragma unroll
            for (int nt = 0; nt < 8; nt++) {
                int col = wn * 64 + nt * 8 + tg * 2;
                if (r0 < N_NODES) {
                    __half2 h = __floats2half2_rn(acc[mt][nt][0], acc[mt][nt][1]);
                    *(__half2*)(g_support + (size_t)r0 * NHID + col) = h;
                }
                if (r8 < N_NODES) {
                    __half2 h = __floats2half2_rn(acc[mt][nt][2], acc[mt][nt][3]);
                    *(__half2*)(g_support + (size_t)r8 * NHID + col) = h;
                }
            }
        }
    }
}

// ===========================================================================
// Edge bucketing: memset(g_cnt) -> fill (no scans).
// ===========================================================================
__global__ __launch_bounds__(256) void fill_kernel(const int* __restrict__ ei,
                                                   const float* __restrict__ ew) {
    int i = blockIdx.x * 256 + threadIdx.x;
    if (i >= N_EDGES) return;
    int src = ei[i];
    int dst = ei[N_EDGES + i];
    int slot = atomicAdd(&g_cnt[dst], 1);
    if (slot < CAP)
        g_edge[(size_t)dst * CAP + slot] = make_int2(src, __float_as_int(ew[i]));
}

// ===========================================================================
// Aggregate: one 16-lane group per dst node (2 nodes/warp). Each lane covers
// 8 columns via uint4 (16B) fp16 loads. 4-edge unroll, 2 accumulator sets.
// Doubles gather MLP per scheduler vs warp-per-node; 4 sectors per edge.
// ===========================================================================
__global__ __launch_bounds__(256) void aggregate_kernel(const float* __restrict__ b,
                                                        float* __restrict__ out) {
    const int grp  = (blockIdx.x * 256 + threadIdx.x) >> 4;   // node id
    const int lane = threadIdx.x & 15;                        // 0..15
    if (grp >= N_NODES) return;

    const size_t base = (size_t)grp * CAP;
    int n = g_cnt[grp];
    if (n > CAP) n = CAP;

    float a0[8], a1[8];
#pragma unroll
    for (int q = 0; q < 8; q++) { a0[q] = 0.f; a1[q] = 0.f; }

    auto fma8 = [&](float* a, uint4 u, float w) {
        float2 f0 = __half22float2(*(__half2*)&u.x);
        float2 f1 = __half22float2(*(__half2*)&u.y);
        float2 f2 = __half22float2(*(__half2*)&u.z);
        float2 f3 = __half22float2(*(__half2*)&u.w);
        a[0] = fmaf(f0.x, w, a[0]); a[1] = fmaf(f0.y, w, a[1]);
        a[2] = fmaf(f1.x, w, a[2]); a[3] = fmaf(f1.y, w, a[3]);
        a[4] = fmaf(f2.x, w, a[4]); a[5] = fmaf(f2.y, w, a[5]);
        a[6] = fmaf(f3.x, w, a[6]); a[7] = fmaf(f3.y, w, a[7]);
    };

    int j = 0;
    for (; j + 4 <= n; j += 4) {
        int2 e0 = __ldg(&g_edge[base + j]);
        int2 e1 = __ldg(&g_edge[base + j + 1]);
        int2 e2 = __ldg(&g_edge[base + j + 2]);
        int2 e3 = __ldg(&g_edge[base + j + 3]);
        uint4 u0 = *(const uint4*)(g_support + (size_t)e0.x * NHID + lane * 8);
        uint4 u1 = *(const uint4*)(g_support + (size_t)e1.x * NHID + lane * 8);
        uint4 u2 = *(const uint4*)(g_support + (size_t)e2.x * NHID + lane * 8);
        uint4 u3 = *(const uint4*)(g_support + (size_t)e3.x * NHID + lane * 8);
        fma8(a0, u0, __int_as_float(e0.y));
        fma8(a1, u1, __int_as_float(e1.y));
        fma8(a0, u2, __int_as_float(e2.y));
        fma8(a1, u3, __int_as_float(e3.y));
    }
    for (; j < n; j++) {
        int2 e0 = __ldg(&g_edge[base + j]);
        uint4 u0 = *(const uint4*)(g_support + (size_t)e0.x * NHID + lane * 8);
        fma8(a0, u0, __int_as_float(e0.y));
    }

    float4 b0 = *(const float4*)(b + lane * 8);
    float4 b1 = *(const float4*)(b + lane * 8 + 4);
    float4 r0, r1;
    r0.x = fmaxf(a0[0] + a1[0] + b0.x, 0.f);
    r0.y = fmaxf(a0[1] + a1[1] + b0.y, 0.f);
    r0.z = fmaxf(a0[2] + a1[2] + b0.z, 0.f);
    r0.w = fmaxf(a0[3] + a1[3] + b0.w, 0.f);
    r1.x = fmaxf(a0[4] + a1[4] + b1.x, 0.f);
    r1.y = fmaxf(a0[5] + a1[5] + b1.y, 0.f);
    r1.z = fmaxf(a0[6] + a1[6] + b1.z, 0.f);
    r1.w = fmaxf(a0[7] + a1[7] + b1.w, 0.f);
    *(float4*)(out + (size_t)grp * NHID + lane * 8)     = r0;
    *(float4*)(out + (size_t)grp * NHID + lane * 8 + 4) = r1;
}

// ===========================================================================
extern "C" void kernel_launch(void* const* d_in, const int* in_sizes, int n_in,
                              void* d_out, int out_size) {
    const float* x  = (const float*)d_in[0];
    const int*   ei = (const int*)d_in[1];     // int32 on device
    const float* ew = (const float*)d_in[2];
    const float* W  = (const float*)d_in[3];
    const float* b  = (const float*)d_in[4];
    float*       out = (float*)d_out;

    const int EDGE_BLKS = (N_EDGES + 255) / 256;

    static cudaStream_t s2 = nullptr;
    static cudaEvent_t evFork = nullptr, evJoin = nullptr;
    if (!s2) {
        cudaStreamCreateWithFlags(&s2, cudaStreamNonBlocking);
        cudaEventCreateWithFlags(&evFork, cudaEventDisableTiming);
        cudaEventCreateWithFlags(&evJoin, cudaEventDisableTiming);
        cudaFuncSetAttribute(gemm_mma_kernel,
                             cudaFuncAttributeMaxDynamicSharedMemorySize, SM_TOT);
    }
    void* cnt_ptr;
    cudaGetSymbolAddress(&cnt_ptr, g_cnt);

    // fork: edge bucketing on s2; split_w + GEMM on the main stream
    cudaEventRecord(evFork, 0);
    cudaStreamWaitEvent(s2, evFork, 0);

    split_w_kernel<<<(NFEAT * NHID) / 256, 256>>>(W);
    gemm_mma_kernel<<<148, 256, SM_TOT>>>(x);

    cudaMemsetAsync(cnt_ptr, 0, N_NODES * sizeof(int), s2);
    fill_kernel<<<EDGE_BLKS, 256, 0, s2>>>(ei, ew);

    // join: aggregate needs support (main) + buckets (s2)
    cudaEventRecord(evJoin, s2);
    cudaStreamWaitEvent(0, evJoin, 0);

    aggregate_kernel<<<(N_NODES * 16 + 255) / 256, 256>>>(b, out);
}

// round 17
// speedup vs baseline: 1.7000x; 1.0968x over previous
#include <cuda_runtime.h>
#include <cuda_bf16.h>
#include <cuda_fp16.h>
#include <cstdint>

#define N_NODES 40000
#define N_EDGES 640000
#define NFEAT   256
#define NHID    128
#define CAP     64          // per-node bucket capacity (degree ~Poisson(16); 64 = 12 sigma)

// ---- device-global scratch (no allocations allowed) ----
__device__ __half g_support[(size_t)N_NODES * NHID];  // x @ W  (fp16 messages)
__device__ int   g_cnt[N_NODES];                // per-dst degree / fill cursor
__device__ int2  g_edge[(size_t)N_NODES * CAP]; // bucketed edges {src, bits(w)}
__device__ __nv_bfloat16 g_wht[(size_t)NHID * NFEAT];     // hi(W^T)  [n][k]
__device__ __nv_bfloat16 g_wlt[(size_t)NHID * NFEAT];     // lo(W^T)  [n][k]

// ===========================================================================
// helpers
// ===========================================================================
__device__ __forceinline__ uint32_t smem_u32(const void* p) {
    uint32_t a;
    asm("{ .reg .u64 t; cvta.to.shared.u64 t, %1; cvt.u32.u64 %0, t; }" : "=r"(a) : "l"(p));
    return a;
}
__device__ __forceinline__ void mma_bf16(float* c, const uint32_t a[4],
                                         uint32_t b0, uint32_t b1) {
    asm volatile(
        "mma.sync.aligned.m16n8k16.row.col.f32.bf16.bf16.f32 "
        "{%0,%1,%2,%3}, {%4,%5,%6,%7}, {%8,%9}, {%0,%1,%2,%3};"
        : "+f"(c[0]), "+f"(c[1]), "+f"(c[2]), "+f"(c[3])
        : "r"(a[0]), "r"(a[1]), "r"(a[2]), "r"(a[3]), "r"(b0), "r"(b1));
}
__device__ __forceinline__ void ldm_x4(uint32_t* r, uint32_t addr) {
    asm volatile("ldmatrix.sync.aligned.m8n8.x4.shared.b16 {%0,%1,%2,%3}, [%4];"
        : "=r"(r[0]), "=r"(r[1]), "=r"(r[2]), "=r"(r[3]) : "r"(addr));
}
__device__ __forceinline__ void cp16(uint32_t dst, const void* src) {
    asm volatile("cp.async.cg.shared.global [%0], [%1], 16;"
        :: "r"(dst), "l"(__cvta_generic_to_global(src)));
}
__device__ __forceinline__ uint32_t packh(float a, float b) {
    return (uint32_t)__bfloat16_as_ushort(__float2bfloat16_rn(a)) |
           ((uint32_t)__bfloat16_as_ushort(__float2bfloat16_rn(b)) << 16);
}

// ===========================================================================
// Pre-split W -> transposed (wht, wlt) bf16  (tiny: 32768 elements)
// ===========================================================================
__global__ __launch_bounds__(256) void split_w_kernel(const float* __restrict__ W) {
    int i = blockIdx.x * 256 + threadIdx.x;
    int k = i >> 7, n = i & 127;
    float v = W[i];
    __nv_bfloat16 h = __float2bfloat16_rn(v);
    __nv_bfloat16 l = __float2bfloat16_rn(v - __bfloat162float(h));
    g_wht[(size_t)n * NFEAT + k] = h;
    g_wlt[(size_t)n * NFEAT + k] = l;
}

// ===========================================================================
// GEMM: persistent CTAs (grid=148), W hi/lo resident in smem (stride 528),
// A fp32 register-staged -> in-register bf16 split -> STS double-buffered
// (stride 80). 3-term mma.sync bf16. ONE sync per K-chunk. fp16 epilogue.
// ===========================================================================
#define NTILES  ((N_NODES + 127) / 128)   // 313
#define STRW    528
#define STRA    80
#define SM_WH   0
#define SM_WL   (128 * STRW)              // 67584
#define SM_A    (2 * 128 * STRW)          // 135168
#define ABUF    (2 * 128 * STRA)          // 20480 (AH + AL)
#define SM_TOT  (SM_A + 2 * ABUF)         // 176128

__global__ __launch_bounds__(256) void gemm_mma_kernel(const float* __restrict__ x) {
    extern __shared__ char sm[];
    const uint32_t sb = smem_u32(sm);
    const int tid = threadIdx.x, wid = tid >> 5, lane = tid & 31;
    const int wm = wid & 3, wn = wid >> 2;      // warp tile: rows wm*32, cols wn*64
    const int g = lane >> 2, tg = lane & 3;
    const int lr = (lane & 7) + ((lane >> 3) & 1) * 8;   // ldmatrix row-in-16
    const int kb = lane >> 4;                             // ldmatrix k-half

    // ---- load W hi/lo into smem once (cp.async, 16B x 4096 per tile) ----
#pragma unroll
    for (int t = 0; t < 16; t++) {
        int idx = tid + t * 256;           // 0..4095
        int n = idx >> 5, cc = idx & 31;
        cp16(sb + SM_WH + n * STRW + cc * 16, g_wht + (size_t)n * NFEAT + cc * 8);
        cp16(sb + SM_WL + n * STRW + cc * 16, g_wlt + (size_t)n * NFEAT + cc * 8);
    }
    asm volatile("cp.async.commit_group;" ::: "memory");

    // per-thread A staging mapping: 4 float4 of the 128x32 fp32 chunk
    const int ar[4] = {(tid + 0)   >> 3, (tid + 256) >> 3,
                       (tid + 512) >> 3, (tid + 768) >> 3};
    const int ac = tid & 7;               // float4 col within row (same all t)

    bool wwait = true;
    for (int tile = blockIdx.x; tile < NTILES; tile += gridDim.x) {
        const int block_row = tile * 128;

        float acc[2][8][4];
#pragma unroll
        for (int mt = 0; mt < 2; mt++)
#pragma unroll
            for (int nt = 0; nt < 8; nt++)
#pragma unroll
                for (int q = 0; q < 4; q++) acc[mt][nt][q] = 0.f;

        float4 pre[4];
        auto ldA = [&](int c) {
#pragma unroll
            for (int t = 0; t < 4; t++) {
                int grow = block_row + ar[t];
                if (grow >= N_NODES) grow = N_NODES - 1;
                pre[t] = *(const float4*)(x + (size_t)grow * NFEAT + c * 32 + ac * 4);
            }
        };
        auto stA = [&](int buf) {
            const uint32_t off0 = SM_A + buf * ABUF;
#pragma unroll
            for (int t = 0; t < 4; t++) {
                float4 v = pre[t];
                uint32_t off = off0 + (uint32_t)(ar[t] * STRA + ac * 8);
                float hx = __bfloat162float(__float2bfloat16_rn(v.x));
                float hy = __bfloat162float(__float2bfloat16_rn(v.y));
                float hz = __bfloat162float(__float2bfloat16_rn(v.z));
                float hw = __bfloat162float(__float2bfloat16_rn(v.w));
                *(uint2*)(sm + off) = make_uint2(packh(v.x, v.y), packh(v.z, v.w));
                *(uint2*)(sm + 128 * STRA + off) =
                    make_uint2(packh(v.x - hx, v.y - hy), packh(v.z - hz, v.w - hw));
            }
        };
        auto compute = [&](int c, int buf) {
            const uint32_t ab = sb + SM_A + buf * ABUF;
#pragma unroll
            for (int ks = 0; ks < 2; ks++) {
                uint32_t ah[2][4], al[2][4];
#pragma unroll
                for (int mt = 0; mt < 2; mt++) {
                    uint32_t off = (uint32_t)((wm * 32 + mt * 16 + lr) * STRA + ks * 32 + kb * 16);
                    ldm_x4(ah[mt], ab + off);
                    ldm_x4(al[mt], ab + 128 * STRA + off);
                }
                const uint32_t kB = (uint32_t)(c * 64 + ks * 32 + kb * 16);
#pragma unroll
                for (int nt2 = 0; nt2 < 4; nt2++) {
                    uint32_t off = (uint32_t)((wn * 64 + nt2 * 16 + lr) * STRW) + kB;
                    uint32_t bh[4], bl[4];
                    ldm_x4(bh, sb + SM_WH + off);
                    ldm_x4(bl, sb + SM_WL + off);
#pragma unroll
                    for (int half = 0; half < 2; half++) {
                        int nt = nt2 * 2 + half;
#pragma unroll
                        for (int mt = 0; mt < 2; mt++) {
                            mma_bf16(acc[mt][nt], ah[mt], bh[half], bh[2 + half]);
                            mma_bf16(acc[mt][nt], ah[mt], bl[half], bl[2 + half]);
                            mma_bf16(acc[mt][nt], al[mt], bh[half], bh[2 + half]);
                        }
                    }
                }
            }
        };

        // prologue: chunk 0 -> buf0, preload chunk 1 into regs
        ldA(0);
        stA(0);
        ldA(1);
        if (wwait) {
            asm volatile("cp.async.wait_group 0;" ::: "memory");
            wwait = false;
        }

        // steady state: ONE sync per chunk.
        // hazards: sync(c) guarantees stA(c) visible (RAW for compute(c)) and
        // compute(c-1) finished (WAR for stA(c+1) into the other buffer).
        for (int c = 0; c < 8; c++) {
            __syncthreads();
            if (c < 7) {
                stA((c + 1) & 1);             // pre holds chunk c+1
                if (c < 6) ldA(c + 2);        // LDG hidden under compute(c)
            }
            compute(c, c & 1);
        }

        // epilogue: fragments -> g_support (fp16, packed half2 stores)
#pragma unroll
        for (int mt = 0; mt < 2; mt++) {
            int r0 = block_row + wm * 32 + mt * 16 + g;
            int r8 = r0 + 8;
#pragma unroll
            for (int nt = 0; nt < 8; nt++) {
                int col = wn * 64 + nt * 8 + tg * 2;
                if (r0 < N_NODES) {
                    __half2 h = __floats2half2_rn(acc[mt][nt][0], acc[mt][nt][1]);
                    *(__half2*)(g_support + (size_t)r0 * NHID + col) = h;
                }
                if (r8 < N_NODES) {
                    __half2 h = __floats2half2_rn(acc[mt][nt][2], acc[mt][nt][3]);
                    *(__half2*)(g_support + (size_t)r8 * NHID + col) = h;
                }
            }
        }
    }
}

// ===========================================================================
// Edge bucketing: memset(g_cnt) -> fill (no scans).
// ===========================================================================
__global__ __launch_bounds__(256) void fill_kernel(const int* __restrict__ ei,
                                                   const float* __restrict__ ew) {
    int i = blockIdx.x * 256 + threadIdx.x;
    if (i >= N_EDGES) return;
    int src = ei[i];
    int dst = ei[N_EDGES + i];
    int slot = atomicAdd(&g_cnt[dst], 1);
    if (slot < CAP)
        g_edge[(size_t)dst * CAP + slot] = make_int2(src, __float_as_int(ew[i]));
}

// ===========================================================================
// Aggregate: one 16-lane group per dst node (2 nodes/warp); fp16 uint4 gather;
// software-pipelined 4-edge batches (next batch's 8 loads in flight during
// current batch's FMAs). Fused bias+relu.
// ===========================================================================
__global__ __launch_bounds__(256) void aggregate_kernel(const float* __restrict__ b,
                                                        float* __restrict__ out) {
    const int grp  = (blockIdx.x * 256 + threadIdx.x) >> 4;   // node id
    const int lane = threadIdx.x & 15;                        // 0..15
    if (grp >= N_NODES) return;

    const size_t base = (size_t)grp * CAP;
    int n = g_cnt[grp];
    if (n > CAP) n = CAP;

    float a0[8], a1[8];
#pragma unroll
    for (int q = 0; q < 8; q++) { a0[q] = 0.f; a1[q] = 0.f; }

    auto fma8 = [&](float* a, const uint4& u, float w) {
        float2 f0 = __half22float2(*(const __half2*)&u.x);
        float2 f1 = __half22float2(*(const __half2*)&u.y);
        float2 f2 = __half22float2(*(const __half2*)&u.z);
        float2 f3 = __half22float2(*(const __half2*)&u.w);
        a[0] = fmaf(f0.x, w, a[0]); a[1] = fmaf(f0.y, w, a[1]);
        a[2] = fmaf(f1.x, w, a[2]); a[3] = fmaf(f1.y, w, a[3]);
        a[4] = fmaf(f2.x, w, a[4]); a[5] = fmaf(f2.y, w, a[5]);
        a[6] = fmaf(f3.x, w, a[6]); a[7] = fmaf(f3.y, w, a[7]);
    };
    auto load4 = [&](int k, int2* e, uint4* u) {
#pragma unroll
        for (int i = 0; i < 4; i++) e[i] = __ldg(&g_edge[base + k + i]);
#pragma unroll
        for (int i = 0; i < 4; i++)
            u[i] = *(const uint4*)(g_support + (size_t)e[i].x * NHID + lane * 8);
    };
    auto fma4 = [&](const int2* e, const uint4* u) {
        fma8(a0, u[0], __int_as_float(e[0].y));
        fma8(a1, u[1], __int_as_float(e[1].y));
        fma8(a0, u[2], __int_as_float(e[2].y));
        fma8(a1, u[3], __int_as_float(e[3].y));
    };

    const int full = n & ~3;
    if (full) {
        int2 e[4]; uint4 u[4];
        load4(0, e, u);                       // prologue
        for (int k = 4; k < full; k += 4) {
            int2 e2[4]; uint4 u2[4];
            load4(k, e2, u2);                 // 8 loads in flight during fma4
            fma4(e, u);
#pragma unroll
            for (int i = 0; i < 4; i++) { e[i] = e2[i]; u[i] = u2[i]; }
        }
        fma4(e, u);
    }
    for (int j = full; j < n; j++) {
        int2 e0 = __ldg(&g_edge[base + j]);
        uint4 u0 = *(const uint4*)(g_support + (size_t)e0.x * NHID + lane * 8);
        fma8(a0, u0, __int_as_float(e0.y));
    }

    float4 b0 = *(const float4*)(b + lane * 8);
    float4 b1 = *(const float4*)(b + lane * 8 + 4);
    float4 r0, r1;
    r0.x = fmaxf(a0[0] + a1[0] + b0.x, 0.f);
    r0.y = fmaxf(a0[1] + a1[1] + b0.y, 0.f);
    r0.z = fmaxf(a0[2] + a1[2] + b0.z, 0.f);
    r0.w = fmaxf(a0[3] + a1[3] + b0.w, 0.f);
    r1.x = fmaxf(a0[4] + a1[4] + b1.x, 0.f);
    r1.y = fmaxf(a0[5] + a1[5] + b1.y, 0.f);
    r1.z = fmaxf(a0[6] + a1[6] + b1.z, 0.f);
    r1.w = fmaxf(a0[7] + a1[7] + b1.w, 0.f);
    *(float4*)(out + (size_t)grp * NHID + lane * 8)     = r0;
    *(float4*)(out + (size_t)grp * NHID + lane * 8 + 4) = r1;
}

// ===========================================================================
extern "C" void kernel_launch(void* const* d_in, const int* in_sizes, int n_in,
                              void* d_out, int out_size) {
    const float* x  = (const float*)d_in[0];
    const int*   ei = (const int*)d_in[1];     // int32 on device
    const float* ew = (const float*)d_in[2];
    const float* W  = (const float*)d_in[3];
    const float* b  = (const float*)d_in[4];
    float*       out = (float*)d_out;

    const int EDGE_BLKS = (N_EDGES + 255) / 256;

    static cudaStream_t s2 = nullptr;
    static cudaEvent_t evFork = nullptr, evJoin = nullptr;
    if (!s2) {
        cudaStreamCreateWithFlags(&s2, cudaStreamNonBlocking);
        cudaEventCreateWithFlags(&evFork, cudaEventDisableTiming);
        cudaEventCreateWithFlags(&evJoin, cudaEventDisableTiming);
        cudaFuncSetAttribute(gemm_mma_kernel,
                             cudaFuncAttributeMaxDynamicSharedMemorySize, SM_TOT);
    }
    void* cnt_ptr;
    cudaGetSymbolAddress(&cnt_ptr, g_cnt);

    // fork: edge bucketing on s2; split_w + GEMM on the main stream
    cudaEventRecord(evFork, 0);
    cudaStreamWaitEvent(s2, evFork, 0);

    split_w_kernel<<<(NFEAT * NHID) / 256, 256>>>(W);
    gemm_mma_kernel<<<148, 256, SM_TOT>>>(x);

    cudaMemsetAsync(cnt_ptr, 0, N_NODES * sizeof(int), s2);
    fill_kernel<<<EDGE_BLKS, 256, 0, s2>>>(ei, ew);

    // join: aggregate needs support (main) + buckets (s2)
    cudaEventRecord(evJoin, s2);
    cudaStreamWaitEvent(0, evJoin, 0);

    aggregate_kernel<<<(N_NODES * 16 + 255) / 256, 256>>>(b, out);
}